// round 13
// baseline (speedup 1.0000x reference)
#include <cuda_runtime.h>
#include <cstdint>

// Problem constants (fixed by the dataset)
#define MAXN   50048
#define MAXE   800000
#define DIN    256
#define DH     256
#define DOUT   64
#define SCAN_B 1024
#define NCHUNK 4

// Scratch (static device globals — no allocation allowed).
__device__ float g_bufA[MAXN * DH];     // GEMM-1 out / GEMM-3 out
__device__ float g_bufB[MAXN * DH];     // gather out (both 256-wide layers)
__device__ float g_bufC[MAXN * DH];     // GEMM-2 out (breaks WAR vs gather-1)
__device__ float g_dis[MAXN];           // deg^{-1/2}
__device__ int   g_cnt[MAXN];           // degree count, then fill cursor
__device__ int   g_rowp[MAXN + 1];      // CSR row pointer
__device__ int   g_blk[128];            // block sums for scan
__device__ int   g_csrc[MAXE];          // CSR src indices

__device__ __forceinline__ float tf32_rna(float x) {
    uint32_t r;
    asm("cvt.rna.tf32.f32 %0, %1;" : "=r"(r) : "f"(x));
    return __uint_as_float(r);
}

#define MMA_TF32(D, Ar, Br) \
    asm volatile("mma.sync.aligned.m16n8k8.row.col.f32.tf32.tf32.f32 " \
        "{%0,%1,%2,%3}, {%4,%5,%6,%7}, {%8,%9}, {%0,%1,%2,%3};" \
        : "+f"((D)[0]), "+f"((D)[1]), "+f"((D)[2]), "+f"((D)[3]) \
        : "r"((Ar)[0]), "r"((Ar)[1]), "r"((Ar)[2]), "r"((Ar)[3]), \
          "r"((Br)[0]), "r"((Br)[1]))

// ===========================================================================
// CSR build + normalization (side stream, overlapped with GEMM-1)
// ===========================================================================
__global__ void k_zero_cnt(int n) {
    int i = blockIdx.x * blockDim.x + threadIdx.x;
    if (i < n) g_cnt[i] = 0;
}

__global__ void k_count(const int* __restrict__ dst, int E, int n) {
    int e = blockIdx.x * blockDim.x + threadIdx.x;
    if (e < E) {
        unsigned d = (unsigned)dst[e];
        if (d < (unsigned)n) atomicAdd(&g_cnt[d], 1);
    }
}

__global__ void k_scan1(int n) {
    __shared__ int sh[SCAN_B];
    int i = blockIdx.x * SCAN_B + threadIdx.x;
    int v = (i < n) ? g_cnt[i] : 0;
    if (i < n) g_dis[i] = rsqrtf((float)(v + 1));
    sh[threadIdx.x] = v;
    __syncthreads();
    #pragma unroll
    for (int off = 1; off < SCAN_B; off <<= 1) {
        int t = (threadIdx.x >= off) ? sh[threadIdx.x - off] : 0;
        __syncthreads();
        sh[threadIdx.x] += t;
        __syncthreads();
    }
    if (i < n) g_rowp[i + 1] = sh[threadIdx.x];
    if (threadIdx.x == SCAN_B - 1) g_blk[blockIdx.x] = sh[SCAN_B - 1];
}

__global__ void k_scan2(int nb) {
    __shared__ int sh[128];
    int v = (threadIdx.x < nb) ? g_blk[threadIdx.x] : 0;
    sh[threadIdx.x] = v;
    __syncthreads();
    #pragma unroll
    for (int off = 1; off < 128; off <<= 1) {
        int t = (threadIdx.x >= off) ? sh[threadIdx.x - off] : 0;
        __syncthreads();
        sh[threadIdx.x] += t;
        __syncthreads();
    }
    if (threadIdx.x < nb)
        g_blk[threadIdx.x] = (threadIdx.x > 0) ? sh[threadIdx.x - 1] : 0;
}

__global__ void k_scan3(int n) {
    int i = blockIdx.x * blockDim.x + threadIdx.x;
    if (i < n) {
        g_rowp[i + 1] += g_blk[i / SCAN_B];
        g_cnt[i] = 0;
    }
    if (i == 0) g_rowp[0] = 0;
}

__global__ void k_fill(const int* __restrict__ src, const int* __restrict__ dst,
                       int E, int n) {
    int e = blockIdx.x * blockDim.x + threadIdx.x;
    if (e >= E) return;
    unsigned s = (unsigned)src[e];
    unsigned d = (unsigned)dst[e];
    if (s >= (unsigned)n || d >= (unsigned)n) return;
    int pos = g_rowp[d] + atomicAdd(&g_cnt[d], 1);
    if (pos < MAXE) g_csrc[pos] = (int)s;
}

// ===========================================================================
// tf32 mma.sync GEMM: dst = A[M,256] @ W[256,Nc], row tiles offset tileOff
// srcSel: 0 = external (x), 1 = g_bufB.   dstSel: 0 = g_bufA, 1 = g_bufC.
// ===========================================================================
template <int BN_>
__global__ __launch_bounds__(256) void k_gemm_mma(
    const float* __restrict__ A_ext, int srcSel, int dstSel,
    const float* __restrict__ W, int M, int Nc, int tileOff)
{
    const float* __restrict__ A = (srcSel == 0) ? A_ext : (const float*)g_bufB;
    float* __restrict__ C = (dstSel == 0) ? (float*)g_bufA : (float*)g_bufC;

    constexpr int WARPS_M = (BN_ == 128) ? 2 : 4;
    constexpr int MT = 8 / WARPS_M;
    constexpr int NT = 4;
    constexpr int F4R = BN_ / 4;
    constexpr int B_IT = BN_ / 32;

    __shared__ float As[128][40];
    __shared__ float Bs[32][BN_ + 8];

    const int tid = threadIdx.x;
    const int lane = tid & 31;
    const int wid = tid >> 5;
    const int wm = wid % WARPS_M;
    const int wn = wid / WARPS_M;
    const int gid = lane >> 2;
    const int tig = lane & 3;
    const int rowBase = (blockIdx.y + tileOff) * 128;
    const int colBase = blockIdx.x * BN_;

    const int la_row = tid >> 3;
    const int la_c4  = tid & 7;
    const int lb_k   = tid / F4R;
    const int lb_c4  = tid % F4R;
    constexpr int LB_STEP = 256 / F4R;

    float acc[MT][NT][4];
    #pragma unroll
    for (int mt = 0; mt < MT; mt++)
        #pragma unroll
        for (int nt = 0; nt < NT; nt++)
            #pragma unroll
            for (int j = 0; j < 4; j++) acc[mt][nt][j] = 0.0f;

    float4 pa[4], pb[B_IT];

    #pragma unroll
    for (int i = 0; i < 4; i++) {
        int grow = rowBase + la_row + i * 32;
        pa[i] = (grow < M) ? ((const float4*)A)[(long long)grow * 64 + la_c4]
                           : make_float4(0.f, 0.f, 0.f, 0.f);
    }
    #pragma unroll
    for (int i = 0; i < B_IT; i++) {
        int k = lb_k + i * LB_STEP;
        pb[i] = *(const float4*)(W + (long long)k * Nc + colBase + lb_c4 * 4);
    }

    #pragma unroll 1
    for (int kb = 0; kb < 8; kb++) {
        #pragma unroll
        for (int i = 0; i < 4; i++) {
            float4 v = pa[i];
            v.x = tf32_rna(v.x); v.y = tf32_rna(v.y);
            v.z = tf32_rna(v.z); v.w = tf32_rna(v.w);
            *(float4*)&As[la_row + i * 32][la_c4 * 4] = v;
        }
        #pragma unroll
        for (int i = 0; i < B_IT; i++) {
            float4 v = pb[i];
            v.x = tf32_rna(v.x); v.y = tf32_rna(v.y);
            v.z = tf32_rna(v.z); v.w = tf32_rna(v.w);
            *(float4*)&Bs[lb_k + i * LB_STEP][lb_c4 * 4] = v;
        }
        __syncthreads();

        if (kb < 7) {
            #pragma unroll
            for (int i = 0; i < 4; i++) {
                int grow = rowBase + la_row + i * 32;
                pa[i] = (grow < M)
                    ? ((const float4*)A)[(long long)grow * 64 + (kb + 1) * 8 + la_c4]
                    : make_float4(0.f, 0.f, 0.f, 0.f);
            }
            #pragma unroll
            for (int i = 0; i < B_IT; i++) {
                int k = (kb + 1) * 32 + lb_k + i * LB_STEP;
                pb[i] = *(const float4*)(W + (long long)k * Nc + colBase + lb_c4 * 4);
            }
        }

        #pragma unroll
        for (int ks = 0; ks < 4; ks++) {
            int k0 = ks * 8;
            uint32_t af[MT][4], bf[NT][2];
            #pragma unroll
            for (int mt = 0; mt < MT; mt++) {
                int m0 = wm * (MT * 16) + mt * 16 + gid;
                af[mt][0] = __float_as_uint(As[m0][k0 + tig]);
                af[mt][1] = __float_as_uint(As[m0 + 8][k0 + tig]);
                af[mt][2] = __float_as_uint(As[m0][k0 + tig + 4]);
                af[mt][3] = __float_as_uint(As[m0 + 8][k0 + tig + 4]);
            }
            #pragma unroll
            for (int nt = 0; nt < NT; nt++) {
                int n0 = wn * 32 + nt * 8 + gid;
                bf[nt][0] = __float_as_uint(Bs[k0 + tig][n0]);
                bf[nt][1] = __float_as_uint(Bs[k0 + tig + 4][n0]);
            }
            #pragma unroll
            for (int mt = 0; mt < MT; mt++)
                #pragma unroll
                for (int nt = 0; nt < NT; nt++)
                    MMA_TF32(acc[mt][nt], af[mt], bf[nt]);
        }
        __syncthreads();
    }

    #pragma unroll
    for (int mt = 0; mt < MT; mt++) {
        int r0 = rowBase + wm * (MT * 16) + mt * 16 + gid;
        int r1 = r0 + 8;
        #pragma unroll
        for (int nt = 0; nt < NT; nt++) {
            int c = colBase + wn * 32 + nt * 8 + tig * 2;
            if (r0 < M)
                *(float2*)(C + (long long)r0 * Nc + c)
                    = make_float2(acc[mt][nt][0], acc[mt][nt][1]);
            if (r1 < M)
                *(float2*)(C + (long long)r1 * Nc + c)
                    = make_float2(acc[mt][nt][2], acc[mt][nt][3]);
        }
    }
}

// ===========================================================================
// CSR gather aggregation over node range [node0, nEnd).
// srcSel: 0 = g_bufA, 1 = g_bufC.   dst: external if useExt else g_bufB.
// ===========================================================================
template <int F, int VPT>
__global__ __launch_bounds__(256) void k_gather(
    float4* __restrict__ dst_ext, int useExt, int srcSel,
    const float* __restrict__ bias, int do_relu, int node0, int nEnd)
{
    const int L = F / (4 * VPT);
    const int F4 = F / 4;
    float4* __restrict__ out = useExt ? dst_ext : (float4*)g_bufB;
    const float4* __restrict__ hs =
        (srcSel == 0) ? (const float4*)g_bufA : (const float4*)g_bufC;

    int node = node0 + blockIdx.x * (256 / L) + threadIdx.x / L;
    if (node >= nEnd) return;
    int lane = threadIdx.x % L;

    float dd = g_dis[node];
    float4 acc[VPT];
    #pragma unroll
    for (int v = 0; v < VPT; v++) {
        float4 t = hs[(long long)node * F4 + lane + v * L];
        acc[v] = make_float4(t.x * dd, t.y * dd, t.z * dd, t.w * dd);
    }

    int p0 = g_rowp[node], p1 = g_rowp[node + 1];
    int p = p0;
    for (; p + 3 < p1; p += 4) {
        int s0 = g_csrc[p + 0];
        int s1 = g_csrc[p + 1];
        int s2 = g_csrc[p + 2];
        int s3 = g_csrc[p + 3];
        float w0 = g_dis[s0], w1 = g_dis[s1], w2 = g_dis[s2], w3 = g_dis[s3];
        #pragma unroll
        for (int v = 0; v < VPT; v++) {
            float4 t0 = hs[(long long)s0 * F4 + lane + v * L];
            float4 t1 = hs[(long long)s1 * F4 + lane + v * L];
            float4 t2 = hs[(long long)s2 * F4 + lane + v * L];
            float4 t3 = hs[(long long)s3 * F4 + lane + v * L];
            acc[v].x += (t0.x * w0 + t1.x * w1) + (t2.x * w2 + t3.x * w3);
            acc[v].y += (t0.y * w0 + t1.y * w1) + (t2.y * w2 + t3.y * w3);
            acc[v].z += (t0.z * w0 + t1.z * w1) + (t2.z * w2 + t3.z * w3);
            acc[v].w += (t0.w * w0 + t1.w * w1) + (t2.w * w2 + t3.w * w3);
        }
    }
    for (; p < p1; p++) {
        int s = g_csrc[p];
        float w = g_dis[s];
        #pragma unroll
        for (int v = 0; v < VPT; v++) {
            float4 t = hs[(long long)s * F4 + lane + v * L];
            acc[v].x += t.x * w; acc[v].y += t.y * w;
            acc[v].z += t.z * w; acc[v].w += t.w * w;
        }
    }

    #pragma unroll
    for (int v = 0; v < VPT; v++) {
        float4 b4 = ((const float4*)bias)[lane + v * L];
        float4 o;
        o.x = acc[v].x * dd + b4.x;
        o.y = acc[v].y * dd + b4.y;
        o.z = acc[v].z * dd + b4.z;
        o.w = acc[v].w * dd + b4.w;
        if (do_relu) {
            o.x = fmaxf(o.x, 0.0f); o.y = fmaxf(o.y, 0.0f);
            o.z = fmaxf(o.z, 0.0f); o.w = fmaxf(o.w, 0.0f);
        }
        out[(long long)node * F4 + lane + v * L] = o;
    }
}

// ===========================================================================
// Launch: CSR on side stream; gather_k chunks pipelined with GEMM_{k+1}
// chunks. Buffers: x -G1-> A -g1-> B -G2-> C -g2-> B -G3-> A -g3-> out.
// ===========================================================================
extern "C" void kernel_launch(void* const* d_in, const int* in_sizes, int n_in,
                              void* d_out, int out_size)
{
    const float* x   = (const float*)d_in[0];
    const int*   ei  = (const int*)d_in[1];
    const float* W1  = (const float*)d_in[2];
    const float* b1  = (const float*)d_in[3];
    const float* W2  = (const float*)d_in[4];
    const float* b2  = (const float*)d_in[5];
    const float* W3  = (const float*)d_in[6];
    const float* b3  = (const float*)d_in[7];
    float*       out = (float*)d_out;

    const int N = in_sizes[0] / DIN;
    const int E = in_sizes[1] / 2;
    const int* srcp = ei;
    const int* dstp = ei + E;

    const int mtiles = (N + 127) / 128;
    const int nb = (N + SCAN_B - 1) / SCAN_B;

    // Chunk boundaries (128-row aligned)
    int tpc = (mtiles + NCHUNK - 1) / NCHUNK;
    int tile0[NCHUNK], tiles[NCHUNK], n0[NCHUNK], n1[NCHUNK];
    for (int c = 0; c < NCHUNK; c++) {
        tile0[c] = c * tpc;
        int te = tile0[c] + tpc; if (te > mtiles) te = mtiles;
        tiles[c] = te - tile0[c]; if (tiles[c] < 0) tiles[c] = 0;
        n0[c] = tile0[c] * 128;
        n1[c] = te * 128; if (n1[c] > N) n1[c] = N;
    }

    static cudaStream_t s2 = nullptr;
    static cudaEvent_t evF = nullptr, evG1 = nullptr, evG2 = nullptr;
    static cudaEvent_t evg1[NCHUNK], evg2[NCHUNK];
    if (!s2) {
        cudaStreamCreateWithFlags(&s2, cudaStreamNonBlocking);
        cudaEventCreateWithFlags(&evF, cudaEventDisableTiming);
        cudaEventCreateWithFlags(&evG1, cudaEventDisableTiming);
        cudaEventCreateWithFlags(&evG2, cudaEventDisableTiming);
        for (int c = 0; c < NCHUNK; c++) {
            cudaEventCreateWithFlags(&evg1[c], cudaEventDisableTiming);
            cudaEventCreateWithFlags(&evg2[c], cudaEventDisableTiming);
        }
    }

    // Fork: CSR build chain on side stream
    cudaEventRecord(evF, 0);
    cudaStreamWaitEvent(s2, evF, 0);
    k_zero_cnt<<<(N + 255) / 256, 256, 0, s2>>>(N);
    k_count<<<(E + 255) / 256, 256, 0, s2>>>(dstp, E, N);
    k_scan1<<<nb, SCAN_B, 0, s2>>>(N);
    k_scan2<<<1, 128, 0, s2>>>(nb);
    k_scan3<<<(N + 255) / 256, 256, 0, s2>>>(N);
    k_fill<<<(E + 255) / 256, 256, 0, s2>>>(srcp, dstp, E, N);

    // Main: layer-1 GEMM: x -> bufA
    k_gemm_mma<128><<<dim3(DH / 128, mtiles), 256>>>(x, 0, 0, W1, N, DH, 0);
    cudaEventRecord(evG1, 0);

    // Side stream: gather-1 chunks: bufA -> bufB
    cudaStreamWaitEvent(s2, evG1, 0);
    for (int c = 0; c < NCHUNK; c++) {
        int nodes = n1[c] - n0[c];
        if (nodes > 0)
            k_gather<DH, 2><<<(nodes + 7) / 8, 256, 0, s2>>>(
                nullptr, 0, 0, b1, 1, n0[c], n1[c]);
        cudaEventRecord(evg1[c], s2);
    }

    // Main: layer-2 GEMM chunks: bufB -> bufC (no WAR vs gather-1 on bufA)
    for (int c = 0; c < NCHUNK; c++) {
        cudaStreamWaitEvent(0, evg1[c], 0);
        if (tiles[c] > 0)
            k_gemm_mma<128><<<dim3(DH / 128, tiles[c]), 256>>>(
                nullptr, 1, 1, W2, N, DH, tile0[c]);
    }
    cudaEventRecord(evG2, 0);

    // Side stream: gather-2 chunks: bufC -> bufB (all GEMM-2 done)
    cudaStreamWaitEvent(s2, evG2, 0);
    for (int c = 0; c < NCHUNK; c++) {
        int nodes = n1[c] - n0[c];
        if (nodes > 0)
            k_gather<DH, 2><<<(nodes + 7) / 8, 256, 0, s2>>>(
                nullptr, 0, 1, b2, 1, n0[c], n1[c]);
        cudaEventRecord(evg2[c], s2);
    }

    // Main: layer-3 GEMM chunks: bufB -> bufA (bufA free since gather-1)
    for (int c = 0; c < NCHUNK; c++) {
        cudaStreamWaitEvent(0, evg2[c], 0);
        if (tiles[c] > 0)
            k_gemm_mma<64><<<dim3(DOUT / 64, tiles[c]), 256>>>(
                nullptr, 1, 0, W3, N, DOUT, tile0[c]);
    }

    // Main: final gather: bufA -> d_out
    k_gather<DOUT, 1><<<(N + 15) / 16, 256>>>((float4*)out, 1, 0, b3, 0, 0, N);
}

// round 14
// speedup vs baseline: 1.0450x; 1.0450x over previous
#include <cuda_runtime.h>
#include <cstdint>

// Problem constants (fixed by the dataset)
#define MAXN   50048
#define MAXE   800000
#define DIN    256
#define DH     256
#define DOUT   64
#define SCAN_B 1024
#define NCHUNK 4

// Scratch (static device globals — no allocation allowed).
__device__ float g_bufA[MAXN * DH];     // GEMM-1/2 out
__device__ float g_bufB[MAXN * DH];     // gather-1/2 out
__device__ float g_bufD[MAXN * DOUT];   // GEMM-3 out (small: keeps L2 set <126MB)
__device__ float g_dis[MAXN];           // deg^{-1/2}
__device__ int   g_cnt[MAXN];           // degree count, then fill cursor
__device__ int   g_rowp[MAXN + 1];      // CSR row pointer
__device__ int   g_blk[128];            // block sums for scan
__device__ int   g_csrc[MAXE];          // CSR src indices

__device__ __forceinline__ float tf32_rna(float x) {
    uint32_t r;
    asm("cvt.rna.tf32.f32 %0, %1;" : "=r"(r) : "f"(x));
    return __uint_as_float(r);
}

#define MMA_TF32(D, Ar, Br) \
    asm volatile("mma.sync.aligned.m16n8k8.row.col.f32.tf32.tf32.f32 " \
        "{%0,%1,%2,%3}, {%4,%5,%6,%7}, {%8,%9}, {%0,%1,%2,%3};" \
        : "+f"((D)[0]), "+f"((D)[1]), "+f"((D)[2]), "+f"((D)[3]) \
        : "r"((Ar)[0]), "r"((Ar)[1]), "r"((Ar)[2]), "r"((Ar)[3]), \
          "r"((Br)[0]), "r"((Br)[1]))

// ===========================================================================
// CSR build + normalization (side stream, overlapped with GEMM-1)
// ===========================================================================
__global__ void k_zero_cnt(int n) {
    int i = blockIdx.x * blockDim.x + threadIdx.x;
    if (i < n) g_cnt[i] = 0;
}

__global__ void k_count(const int* __restrict__ dst, int E, int n) {
    int e = blockIdx.x * blockDim.x + threadIdx.x;
    if (e < E) {
        unsigned d = (unsigned)dst[e];
        if (d < (unsigned)n) atomicAdd(&g_cnt[d], 1);
    }
}

__global__ void k_scan1(int n) {
    __shared__ int sh[SCAN_B];
    int i = blockIdx.x * SCAN_B + threadIdx.x;
    int v = (i < n) ? g_cnt[i] : 0;
    if (i < n) g_dis[i] = rsqrtf((float)(v + 1));
    sh[threadIdx.x] = v;
    __syncthreads();
    #pragma unroll
    for (int off = 1; off < SCAN_B; off <<= 1) {
        int t = (threadIdx.x >= off) ? sh[threadIdx.x - off] : 0;
        __syncthreads();
        sh[threadIdx.x] += t;
        __syncthreads();
    }
    if (i < n) g_rowp[i + 1] = sh[threadIdx.x];
    if (threadIdx.x == SCAN_B - 1) g_blk[blockIdx.x] = sh[SCAN_B - 1];
}

__global__ void k_scan2(int nb) {
    __shared__ int sh[128];
    int v = (threadIdx.x < nb) ? g_blk[threadIdx.x] : 0;
    sh[threadIdx.x] = v;
    __syncthreads();
    #pragma unroll
    for (int off = 1; off < 128; off <<= 1) {
        int t = (threadIdx.x >= off) ? sh[threadIdx.x - off] : 0;
        __syncthreads();
        sh[threadIdx.x] += t;
        __syncthreads();
    }
    if (threadIdx.x < nb)
        g_blk[threadIdx.x] = (threadIdx.x > 0) ? sh[threadIdx.x - 1] : 0;
}

__global__ void k_scan3(int n) {
    int i = blockIdx.x * blockDim.x + threadIdx.x;
    if (i < n) {
        g_rowp[i + 1] += g_blk[i / SCAN_B];
        g_cnt[i] = 0;
    }
    if (i == 0) g_rowp[0] = 0;
}

__global__ void k_fill(const int* __restrict__ src, const int* __restrict__ dst,
                       int E, int n) {
    int e = blockIdx.x * blockDim.x + threadIdx.x;
    if (e >= E) return;
    unsigned s = (unsigned)src[e];
    unsigned d = (unsigned)dst[e];
    if (s >= (unsigned)n || d >= (unsigned)n) return;
    int pos = g_rowp[d] + atomicAdd(&g_cnt[d], 1);
    if (pos < MAXE) g_csrc[pos] = (int)s;
}

// ===========================================================================
// tf32 mma.sync GEMM: dst = A[M,256] @ W[256,Nc], row tiles offset tileOff
// srcSel: 0 = external (x), 1 = g_bufB.   dstSel: 0 = g_bufA, 1 = g_bufD.
// ===========================================================================
template <int BN_>
__global__ __launch_bounds__(256) void k_gemm_mma(
    const float* __restrict__ A_ext, int srcSel, int dstSel,
    const float* __restrict__ W, int M, int Nc, int tileOff)
{
    const float* __restrict__ A = (srcSel == 0) ? A_ext : (const float*)g_bufB;
    float* __restrict__ C = (dstSel == 0) ? (float*)g_bufA : (float*)g_bufD;

    constexpr int WARPS_M = (BN_ == 128) ? 2 : 4;
    constexpr int MT = 8 / WARPS_M;
    constexpr int NT = 4;
    constexpr int F4R = BN_ / 4;
    constexpr int B_IT = BN_ / 32;

    __shared__ float As[128][40];
    __shared__ float Bs[32][BN_ + 8];

    const int tid = threadIdx.x;
    const int lane = tid & 31;
    const int wid = tid >> 5;
    const int wm = wid % WARPS_M;
    const int wn = wid / WARPS_M;
    const int gid = lane >> 2;
    const int tig = lane & 3;
    const int rowBase = (blockIdx.y + tileOff) * 128;
    const int colBase = blockIdx.x * BN_;

    const int la_row = tid >> 3;
    const int la_c4  = tid & 7;
    const int lb_k   = tid / F4R;
    const int lb_c4  = tid % F4R;
    constexpr int LB_STEP = 256 / F4R;

    float acc[MT][NT][4];
    #pragma unroll
    for (int mt = 0; mt < MT; mt++)
        #pragma unroll
        for (int nt = 0; nt < NT; nt++)
            #pragma unroll
            for (int j = 0; j < 4; j++) acc[mt][nt][j] = 0.0f;

    float4 pa[4], pb[B_IT];

    #pragma unroll
    for (int i = 0; i < 4; i++) {
        int grow = rowBase + la_row + i * 32;
        pa[i] = (grow < M) ? ((const float4*)A)[(long long)grow * 64 + la_c4]
                           : make_float4(0.f, 0.f, 0.f, 0.f);
    }
    #pragma unroll
    for (int i = 0; i < B_IT; i++) {
        int k = lb_k + i * LB_STEP;
        pb[i] = *(const float4*)(W + (long long)k * Nc + colBase + lb_c4 * 4);
    }

    #pragma unroll 1
    for (int kb = 0; kb < 8; kb++) {
        #pragma unroll
        for (int i = 0; i < 4; i++) {
            float4 v = pa[i];
            v.x = tf32_rna(v.x); v.y = tf32_rna(v.y);
            v.z = tf32_rna(v.z); v.w = tf32_rna(v.w);
            *(float4*)&As[la_row + i * 32][la_c4 * 4] = v;
        }
        #pragma unroll
        for (int i = 0; i < B_IT; i++) {
            float4 v = pb[i];
            v.x = tf32_rna(v.x); v.y = tf32_rna(v.y);
            v.z = tf32_rna(v.z); v.w = tf32_rna(v.w);
            *(float4*)&Bs[lb_k + i * LB_STEP][lb_c4 * 4] = v;
        }
        __syncthreads();

        if (kb < 7) {
            #pragma unroll
            for (int i = 0; i < 4; i++) {
                int grow = rowBase + la_row + i * 32;
                pa[i] = (grow < M)
                    ? ((const float4*)A)[(long long)grow * 64 + (kb + 1) * 8 + la_c4]
                    : make_float4(0.f, 0.f, 0.f, 0.f);
            }
            #pragma unroll
            for (int i = 0; i < B_IT; i++) {
                int k = (kb + 1) * 32 + lb_k + i * LB_STEP;
                pb[i] = *(const float4*)(W + (long long)k * Nc + colBase + lb_c4 * 4);
            }
        }

        #pragma unroll
        for (int ks = 0; ks < 4; ks++) {
            int k0 = ks * 8;
            uint32_t af[MT][4], bf[NT][2];
            #pragma unroll
            for (int mt = 0; mt < MT; mt++) {
                int m0 = wm * (MT * 16) + mt * 16 + gid;
                af[mt][0] = __float_as_uint(As[m0][k0 + tig]);
                af[mt][1] = __float_as_uint(As[m0 + 8][k0 + tig]);
                af[mt][2] = __float_as_uint(As[m0][k0 + tig + 4]);
                af[mt][3] = __float_as_uint(As[m0 + 8][k0 + tig + 4]);
            }
            #pragma unroll
            for (int nt = 0; nt < NT; nt++) {
                int n0 = wn * 32 + nt * 8 + gid;
                bf[nt][0] = __float_as_uint(Bs[k0 + tig][n0]);
                bf[nt][1] = __float_as_uint(Bs[k0 + tig + 4][n0]);
            }
            #pragma unroll
            for (int mt = 0; mt < MT; mt++)
                #pragma unroll
                for (int nt = 0; nt < NT; nt++)
                    MMA_TF32(acc[mt][nt], af[mt], bf[nt]);
        }
        __syncthreads();
    }

    #pragma unroll
    for (int mt = 0; mt < MT; mt++) {
        int r0 = rowBase + wm * (MT * 16) + mt * 16 + gid;
        int r1 = r0 + 8;
        #pragma unroll
        for (int nt = 0; nt < NT; nt++) {
            int c = colBase + wn * 32 + nt * 8 + tig * 2;
            if (r0 < M)
                *(float2*)(C + (long long)r0 * Nc + c)
                    = make_float2(acc[mt][nt][0], acc[mt][nt][1]);
            if (r1 < M)
                *(float2*)(C + (long long)r1 * Nc + c)
                    = make_float2(acc[mt][nt][2], acc[mt][nt][3]);
        }
    }
}

// ===========================================================================
// CSR gather aggregation over node range [node0, nEnd).
// srcSel: 0 = g_bufA, 1 = g_bufD.   dst: external if useExt else g_bufB.
// ===========================================================================
template <int F, int VPT>
__global__ __launch_bounds__(256) void k_gather(
    float4* __restrict__ dst_ext, int useExt, int srcSel,
    const float* __restrict__ bias, int do_relu, int node0, int nEnd)
{
    const int L = F / (4 * VPT);
    const int F4 = F / 4;
    float4* __restrict__ out = useExt ? dst_ext : (float4*)g_bufB;
    const float4* __restrict__ hs =
        (srcSel == 0) ? (const float4*)g_bufA : (const float4*)g_bufD;

    int node = node0 + blockIdx.x * (256 / L) + threadIdx.x / L;
    if (node >= nEnd) return;
    int lane = threadIdx.x % L;

    float dd = g_dis[node];
    float4 acc[VPT];
    #pragma unroll
    for (int v = 0; v < VPT; v++) {
        float4 t = hs[(long long)node * F4 + lane + v * L];
        acc[v] = make_float4(t.x * dd, t.y * dd, t.z * dd, t.w * dd);
    }

    int p0 = g_rowp[node], p1 = g_rowp[node + 1];
    int p = p0;
    for (; p + 3 < p1; p += 4) {
        int s0 = g_csrc[p + 0];
        int s1 = g_csrc[p + 1];
        int s2 = g_csrc[p + 2];
        int s3 = g_csrc[p + 3];
        float w0 = g_dis[s0], w1 = g_dis[s1], w2 = g_dis[s2], w3 = g_dis[s3];
        #pragma unroll
        for (int v = 0; v < VPT; v++) {
            float4 t0 = hs[(long long)s0 * F4 + lane + v * L];
            float4 t1 = hs[(long long)s1 * F4 + lane + v * L];
            float4 t2 = hs[(long long)s2 * F4 + lane + v * L];
            float4 t3 = hs[(long long)s3 * F4 + lane + v * L];
            acc[v].x += (t0.x * w0 + t1.x * w1) + (t2.x * w2 + t3.x * w3);
            acc[v].y += (t0.y * w0 + t1.y * w1) + (t2.y * w2 + t3.y * w3);
            acc[v].z += (t0.z * w0 + t1.z * w1) + (t2.z * w2 + t3.z * w3);
            acc[v].w += (t0.w * w0 + t1.w * w1) + (t2.w * w2 + t3.w * w3);
        }
    }
    for (; p < p1; p++) {
        int s = g_csrc[p];
        float w = g_dis[s];
        #pragma unroll
        for (int v = 0; v < VPT; v++) {
            float4 t = hs[(long long)s * F4 + lane + v * L];
            acc[v].x += t.x * w; acc[v].y += t.y * w;
            acc[v].z += t.z * w; acc[v].w += t.w * w;
        }
    }

    #pragma unroll
    for (int v = 0; v < VPT; v++) {
        float4 b4 = ((const float4*)bias)[lane + v * L];
        float4 o;
        o.x = acc[v].x * dd + b4.x;
        o.y = acc[v].y * dd + b4.y;
        o.z = acc[v].z * dd + b4.z;
        o.w = acc[v].w * dd + b4.w;
        if (do_relu) {
            o.x = fmaxf(o.x, 0.0f); o.y = fmaxf(o.y, 0.0f);
            o.z = fmaxf(o.z, 0.0f); o.w = fmaxf(o.w, 0.0f);
        }
        out[(long long)node * F4 + lane + v * L] = o;
    }
}

// ===========================================================================
// Launch. Linear R8 schedule + one safe overlap:
//   x -G1-> A -g1-> B -G2-> A -g2-> B -G3-> D -g3-> out
// CSR build ∥ G1 (side stream).  g2 chunks (main) ∥ G3 chunks (side, ->D).
// Live set during g2/G3 overlap: A+B+D = 115MB < 126MB L2 (no thrash).
// ===========================================================================
extern "C" void kernel_launch(void* const* d_in, const int* in_sizes, int n_in,
                              void* d_out, int out_size)
{
    const float* x   = (const float*)d_in[0];
    const int*   ei  = (const int*)d_in[1];
    const float* W1  = (const float*)d_in[2];
    const float* b1  = (const float*)d_in[3];
    const float* W2  = (const float*)d_in[4];
    const float* b2  = (const float*)d_in[5];
    const float* W3  = (const float*)d_in[6];
    const float* b3  = (const float*)d_in[7];
    float*       out = (float*)d_out;

    const int N = in_sizes[0] / DIN;
    const int E = in_sizes[1] / 2;
    const int* srcp = ei;
    const int* dstp = ei + E;

    const int mtiles = (N + 127) / 128;
    const int nb = (N + SCAN_B - 1) / SCAN_B;

    // Chunk boundaries for the g2/G3 pipeline (128-row aligned)
    int tpc = (mtiles + NCHUNK - 1) / NCHUNK;
    int tile0[NCHUNK], tiles[NCHUNK], n0[NCHUNK], n1[NCHUNK];
    for (int c = 0; c < NCHUNK; c++) {
        tile0[c] = c * tpc;
        int te = tile0[c] + tpc; if (te > mtiles) te = mtiles;
        tiles[c] = te - tile0[c]; if (tiles[c] < 0) tiles[c] = 0;
        n0[c] = tile0[c] * 128;
        n1[c] = te * 128; if (n1[c] > N) n1[c] = N;
    }

    static cudaStream_t s2 = nullptr;
    static cudaEvent_t evF = nullptr, evCSR = nullptr, evD = nullptr;
    static cudaEvent_t evg2[NCHUNK];
    if (!s2) {
        cudaStreamCreateWithFlags(&s2, cudaStreamNonBlocking);
        cudaEventCreateWithFlags(&evF, cudaEventDisableTiming);
        cudaEventCreateWithFlags(&evCSR, cudaEventDisableTiming);
        cudaEventCreateWithFlags(&evD, cudaEventDisableTiming);
        for (int c = 0; c < NCHUNK; c++)
            cudaEventCreateWithFlags(&evg2[c], cudaEventDisableTiming);
    }

    // Fork: CSR build chain on side stream (overlaps GEMM-1)
    cudaEventRecord(evF, 0);
    cudaStreamWaitEvent(s2, evF, 0);
    k_zero_cnt<<<(N + 255) / 256, 256, 0, s2>>>(N);
    k_count<<<(E + 255) / 256, 256, 0, s2>>>(dstp, E, N);
    k_scan1<<<nb, SCAN_B, 0, s2>>>(N);
    k_scan2<<<1, 128, 0, s2>>>(nb);
    k_scan3<<<(N + 255) / 256, 256, 0, s2>>>(N);
    k_fill<<<(E + 255) / 256, 256, 0, s2>>>(srcp, dstp, E, N);
    cudaEventRecord(evCSR, s2);

    // Main: G1: x -> A
    k_gemm_mma<128><<<dim3(DH / 128, mtiles), 256>>>(x, 0, 0, W1, N, DH, 0);
    cudaStreamWaitEvent(0, evCSR, 0);

    // Main: g1: A -> B (full)
    k_gather<DH, 2><<<(N + 7) / 8, 256>>>(nullptr, 0, 0, b1, 1, 0, N);

    // Main: G2: B -> A (full)
    k_gemm_mma<128><<<dim3(DH / 128, mtiles), 256>>>(nullptr, 1, 0, W2, N, DH, 0);

    // Pipelined boundary: g2 chunks (main, A->B) ∥ G3 chunks (side, B->D)
    for (int c = 0; c < NCHUNK; c++) {
        int nodes = n1[c] - n0[c];
        if (nodes > 0)
            k_gather<DH, 2><<<(nodes + 7) / 8, 256>>>(
                nullptr, 0, 0, b2, 1, n0[c], n1[c]);
        cudaEventRecord(evg2[c], 0);
        cudaStreamWaitEvent(s2, evg2[c], 0);
        if (tiles[c] > 0)
            k_gemm_mma<64><<<dim3(DOUT / 64, tiles[c]), 256, 0, s2>>>(
                nullptr, 1, 1, W3, N, DOUT, tile0[c]);
    }
    cudaEventRecord(evD, s2);
    cudaStreamWaitEvent(0, evD, 0);

    // Main: g3: D -> out (full)
    k_gather<DOUT, 1><<<(N + 15) / 16, 256>>>((float4*)out, 1, 1, b3, 0, 0, N);
}

// round 16
// speedup vs baseline: 1.1666x; 1.1164x over previous
#include <cuda_runtime.h>
#include <cstdint>

// Problem constants (fixed by the dataset)
#define MAXN   50048
#define MAXE   800000
#define DIN    256
#define DH     256
#define DOUT   64
#define SCAN_B 1024

// Scratch (static device globals — no allocation allowed).
__device__ float g_bufA[MAXN * DH];     // GEMM out (all layers)
__device__ float g_bufB[MAXN * DH];     // gather out (tf32-rounded)
__device__ float g_W2r[DH * DH];        // pre-rounded W2
__device__ float g_W3r[DH * DOUT];      // pre-rounded W3
__device__ float g_dis[MAXN];           // deg^{-1/2}
__device__ int   g_cnt[MAXN];           // degree count, then fill cursor
__device__ int   g_rowp[MAXN + 1];      // CSR row pointer
__device__ int   g_blk[128];            // block sums for scan
__device__ int   g_csrc[MAXE];          // CSR src indices

__device__ __forceinline__ float tf32_rna(float x) {
    uint32_t r;
    asm("cvt.rna.tf32.f32 %0, %1;" : "=r"(r) : "f"(x));
    return __uint_as_float(r);
}

#define MMA_TF32(D, Ar, Br) \
    asm volatile("mma.sync.aligned.m16n8k8.row.col.f32.tf32.tf32.f32 " \
        "{%0,%1,%2,%3}, {%4,%5,%6,%7}, {%8,%9}, {%0,%1,%2,%3};" \
        : "+f"((D)[0]), "+f"((D)[1]), "+f"((D)[2]), "+f"((D)[3]) \
        : "r"((Ar)[0]), "r"((Ar)[1]), "r"((Ar)[2]), "r"((Ar)[3]), \
          "r"((Br)[0]), "r"((Br)[1]))

// ===========================================================================
// Weight pre-rounding (side stream, hidden under GEMM-1)
// ===========================================================================
__global__ void k_round_w(const float* __restrict__ src, int which, int n) {
    float* dst = (which == 0) ? (float*)g_W2r : (float*)g_W3r;
    int i = blockIdx.x * blockDim.x + threadIdx.x;
    if (i < n) dst[i] = tf32_rna(src[i]);
}

// ===========================================================================
// CSR build + normalization (side stream, overlapped with GEMM-1)
// ===========================================================================
__global__ void k_zero_cnt(int n) {
    int i = blockIdx.x * blockDim.x + threadIdx.x;
    if (i < n) g_cnt[i] = 0;
}

__global__ void k_count(const int* __restrict__ dst, int E, int n) {
    int e = blockIdx.x * blockDim.x + threadIdx.x;
    if (e < E) {
        unsigned d = (unsigned)dst[e];
        if (d < (unsigned)n) atomicAdd(&g_cnt[d], 1);
    }
}

__global__ void k_scan1(int n) {
    __shared__ int sh[SCAN_B];
    int i = blockIdx.x * SCAN_B + threadIdx.x;
    int v = (i < n) ? g_cnt[i] : 0;
    if (i < n) g_dis[i] = rsqrtf((float)(v + 1));
    sh[threadIdx.x] = v;
    __syncthreads();
    #pragma unroll
    for (int off = 1; off < SCAN_B; off <<= 1) {
        int t = (threadIdx.x >= off) ? sh[threadIdx.x - off] : 0;
        __syncthreads();
        sh[threadIdx.x] += t;
        __syncthreads();
    }
    if (i < n) g_rowp[i + 1] = sh[threadIdx.x];
    if (threadIdx.x == SCAN_B - 1) g_blk[blockIdx.x] = sh[SCAN_B - 1];
}

__global__ void k_scan2(int nb) {
    __shared__ int sh[128];
    int v = (threadIdx.x < nb) ? g_blk[threadIdx.x] : 0;
    sh[threadIdx.x] = v;
    __syncthreads();
    #pragma unroll
    for (int off = 1; off < 128; off <<= 1) {
        int t = (threadIdx.x >= off) ? sh[threadIdx.x - off] : 0;
        __syncthreads();
        sh[threadIdx.x] += t;
        __syncthreads();
    }
    if (threadIdx.x < nb)
        g_blk[threadIdx.x] = (threadIdx.x > 0) ? sh[threadIdx.x - 1] : 0;
}

__global__ void k_scan3(int n) {
    int i = blockIdx.x * blockDim.x + threadIdx.x;
    if (i < n) {
        g_rowp[i + 1] += g_blk[i / SCAN_B];
        g_cnt[i] = 0;
    }
    if (i == 0) g_rowp[0] = 0;
}

__global__ void k_fill(const int* __restrict__ src, const int* __restrict__ dst,
                       int E, int n) {
    int e = blockIdx.x * blockDim.x + threadIdx.x;
    if (e >= E) return;
    unsigned s = (unsigned)src[e];
    unsigned d = (unsigned)dst[e];
    if (s >= (unsigned)n || d >= (unsigned)n) return;
    int pos = g_rowp[d] + atomicAdd(&g_cnt[d], 1);
    if (pos < MAXE) g_csrc[pos] = (int)s;
}

// ===========================================================================
// tf32 mma.sync GEMM: g_bufA = A[M,256] @ W[256,Nc]
// srcSel: 0 = external (x), 1 = g_bufB (already tf32-rounded).
// wSel:   0 = external W arg, 1 = g_W2r, 2 = g_W3r (device symbols resolved
//         IN DEVICE CODE — host cannot pass __device__ array addresses).
// ROUND:  1 = tf32-round on SMEM store (layer 1), 0 = inputs pre-rounded.
// ===========================================================================
template <int BN_, int ROUND>
__global__ __launch_bounds__(256) void k_gemm_mma(
    const float* __restrict__ A_ext, int srcSel,
    const float* __restrict__ W_ext, int wSel, int M, int Nc, int tileOff)
{
    const float* __restrict__ A = (srcSel == 0) ? A_ext : (const float*)g_bufB;
    const float* __restrict__ W =
        (wSel == 0) ? W_ext : ((wSel == 1) ? (const float*)g_W2r
                                           : (const float*)g_W3r);
    float* __restrict__ C = (float*)g_bufA;

    constexpr int WARPS_M = (BN_ == 128) ? 2 : 4;
    constexpr int MT = 8 / WARPS_M;
    constexpr int NT = 4;
    constexpr int F4R = BN_ / 4;
    constexpr int B_IT = BN_ / 32;

    __shared__ float As[128][40];
    __shared__ float Bs[32][BN_ + 8];

    const int tid = threadIdx.x;
    const int lane = tid & 31;
    const int wid = tid >> 5;
    const int wm = wid % WARPS_M;
    const int wn = wid / WARPS_M;
    const int gid = lane >> 2;
    const int tig = lane & 3;
    const int rowBase = (blockIdx.y + tileOff) * 128;
    const int colBase = blockIdx.x * BN_;

    const int la_row = tid >> 3;
    const int la_c4  = tid & 7;
    const int lb_k   = tid / F4R;
    const int lb_c4  = tid % F4R;
    constexpr int LB_STEP = 256 / F4R;

    float acc[MT][NT][4];
    #pragma unroll
    for (int mt = 0; mt < MT; mt++)
        #pragma unroll
        for (int nt = 0; nt < NT; nt++)
            #pragma unroll
            for (int j = 0; j < 4; j++) acc[mt][nt][j] = 0.0f;

    float4 pa[4], pb[B_IT];

    #pragma unroll
    for (int i = 0; i < 4; i++) {
        int grow = rowBase + la_row + i * 32;
        pa[i] = (grow < M) ? ((const float4*)A)[(long long)grow * 64 + la_c4]
                           : make_float4(0.f, 0.f, 0.f, 0.f);
    }
    #pragma unroll
    for (int i = 0; i < B_IT; i++) {
        int k = lb_k + i * LB_STEP;
        pb[i] = *(const float4*)(W + (long long)k * Nc + colBase + lb_c4 * 4);
    }

    #pragma unroll 1
    for (int kb = 0; kb < 8; kb++) {
        #pragma unroll
        for (int i = 0; i < 4; i++) {
            float4 v = pa[i];
            if (ROUND) {
                v.x = tf32_rna(v.x); v.y = tf32_rna(v.y);
                v.z = tf32_rna(v.z); v.w = tf32_rna(v.w);
            }
            *(float4*)&As[la_row + i * 32][la_c4 * 4] = v;
        }
        #pragma unroll
        for (int i = 0; i < B_IT; i++) {
            float4 v = pb[i];
            if (ROUND) {
                v.x = tf32_rna(v.x); v.y = tf32_rna(v.y);
                v.z = tf32_rna(v.z); v.w = tf32_rna(v.w);
            }
            *(float4*)&Bs[lb_k + i * LB_STEP][lb_c4 * 4] = v;
        }
        __syncthreads();

        if (kb < 7) {
            #pragma unroll
            for (int i = 0; i < 4; i++) {
                int grow = rowBase + la_row + i * 32;
                pa[i] = (grow < M)
                    ? ((const float4*)A)[(long long)grow * 64 + (kb + 1) * 8 + la_c4]
                    : make_float4(0.f, 0.f, 0.f, 0.f);
            }
            #pragma unroll
            for (int i = 0; i < B_IT; i++) {
                int k = (kb + 1) * 32 + lb_k + i * LB_STEP;
                pb[i] = *(const float4*)(W + (long long)k * Nc + colBase + lb_c4 * 4);
            }
        }

        #pragma unroll
        for (int ks = 0; ks < 4; ks++) {
            int k0 = ks * 8;
            uint32_t af[MT][4], bf[NT][2];
            #pragma unroll
            for (int mt = 0; mt < MT; mt++) {
                int m0 = wm * (MT * 16) + mt * 16 + gid;
                af[mt][0] = __float_as_uint(As[m0][k0 + tig]);
                af[mt][1] = __float_as_uint(As[m0 + 8][k0 + tig]);
                af[mt][2] = __float_as_uint(As[m0][k0 + tig + 4]);
                af[mt][3] = __float_as_uint(As[m0 + 8][k0 + tig + 4]);
            }
            #pragma unroll
            for (int nt = 0; nt < NT; nt++) {
                int n0 = wn * 32 + nt * 8 + gid;
                bf[nt][0] = __float_as_uint(Bs[k0 + tig][n0]);
                bf[nt][1] = __float_as_uint(Bs[k0 + tig + 4][n0]);
            }
            #pragma unroll
            for (int mt = 0; mt < MT; mt++)
                #pragma unroll
                for (int nt = 0; nt < NT; nt++)
                    MMA_TF32(acc[mt][nt], af[mt], bf[nt]);
        }
        __syncthreads();
    }

    #pragma unroll
    for (int mt = 0; mt < MT; mt++) {
        int r0 = rowBase + wm * (MT * 16) + mt * 16 + gid;
        int r1 = r0 + 8;
        #pragma unroll
        for (int nt = 0; nt < NT; nt++) {
            int c = colBase + wn * 32 + nt * 8 + tig * 2;
            if (r0 < M)
                *(float2*)(C + (long long)r0 * Nc + c)
                    = make_float2(acc[mt][nt][0], acc[mt][nt][1]);
            if (r1 < M)
                *(float2*)(C + (long long)r1 * Nc + c)
                    = make_float2(acc[mt][nt][2], acc[mt][nt][3]);
        }
    }
}

// ===========================================================================
// CSR gather aggregation: src = g_bufA; dst = ext (fp32) or g_bufB.
// ROUNDOUT: tf32-round stored values (so next GEMM can skip cvt).
// Bit-identical to rounding at GEMM load: relu/round commute, bias in fp32.
// ===========================================================================
template <int F, int VPT, int ROUNDOUT>
__global__ __launch_bounds__(256) void k_gather(
    float4* __restrict__ dst_ext, int useExt,
    const float* __restrict__ bias, int do_relu, int node0, int nEnd)
{
    const int L = F / (4 * VPT);
    const int F4 = F / 4;
    float4* __restrict__ out = useExt ? dst_ext : (float4*)g_bufB;
    const float4* __restrict__ hs = (const float4*)g_bufA;

    int node = node0 + blockIdx.x * (256 / L) + threadIdx.x / L;
    if (node >= nEnd) return;
    int lane = threadIdx.x % L;

    float dd = g_dis[node];
    float4 acc[VPT];
    #pragma unroll
    for (int v = 0; v < VPT; v++) {
        float4 t = hs[(long long)node * F4 + lane + v * L];
        acc[v] = make_float4(t.x * dd, t.y * dd, t.z * dd, t.w * dd);
    }

    int p0 = g_rowp[node], p1 = g_rowp[node + 1];
    int p = p0;
    for (; p + 3 < p1; p += 4) {
        int s0 = g_csrc[p + 0];
        int s1 = g_csrc[p + 1];
        int s2 = g_csrc[p + 2];
        int s3 = g_csrc[p + 3];
        float w0 = g_dis[s0], w1 = g_dis[s1], w2 = g_dis[s2], w3 = g_dis[s3];
        #pragma unroll
        for (int v = 0; v < VPT; v++) {
            float4 t0 = hs[(long long)s0 * F4 + lane + v * L];
            float4 t1 = hs[(long long)s1 * F4 + lane + v * L];
            float4 t2 = hs[(long long)s2 * F4 + lane + v * L];
            float4 t3 = hs[(long long)s3 * F4 + lane + v * L];
            acc[v].x += (t0.x * w0 + t1.x * w1) + (t2.x * w2 + t3.x * w3);
            acc[v].y += (t0.y * w0 + t1.y * w1) + (t2.y * w2 + t3.y * w3);
            acc[v].z += (t0.z * w0 + t1.z * w1) + (t2.z * w2 + t3.z * w3);
            acc[v].w += (t0.w * w0 + t1.w * w1) + (t2.w * w2 + t3.w * w3);
        }
    }
    for (; p < p1; p++) {
        int s = g_csrc[p];
        float w = g_dis[s];
        #pragma unroll
        for (int v = 0; v < VPT; v++) {
            float4 t = hs[(long long)s * F4 + lane + v * L];
            acc[v].x += t.x * w; acc[v].y += t.y * w;
            acc[v].z += t.z * w; acc[v].w += t.w * w;
        }
    }

    #pragma unroll
    for (int v = 0; v < VPT; v++) {
        float4 b4 = ((const float4*)bias)[lane + v * L];
        float4 o;
        o.x = acc[v].x * dd + b4.x;
        o.y = acc[v].y * dd + b4.y;
        o.z = acc[v].z * dd + b4.z;
        o.w = acc[v].w * dd + b4.w;
        if (do_relu) {
            o.x = fmaxf(o.x, 0.0f); o.y = fmaxf(o.y, 0.0f);
            o.z = fmaxf(o.z, 0.0f); o.w = fmaxf(o.w, 0.0f);
        }
        if (ROUNDOUT) {
            o.x = tf32_rna(o.x); o.y = tf32_rna(o.y);
            o.z = tf32_rna(o.z); o.w = tf32_rna(o.w);
        }
        out[(long long)node * F4 + lane + v * L] = o;
    }
}

// ===========================================================================
// Launch: exact R8 linear schedule.  x -G1-> A -g1-> B -G2-> A -g2-> B
// -G3-> A -g3-> out.  CSR build + weight pre-round ∥ G1 on side stream.
// ===========================================================================
extern "C" void kernel_launch(void* const* d_in, const int* in_sizes, int n_in,
                              void* d_out, int out_size)
{
    const float* x   = (const float*)d_in[0];
    const int*   ei  = (const int*)d_in[1];
    const float* W1  = (const float*)d_in[2];
    const float* b1  = (const float*)d_in[3];
    const float* W2  = (const float*)d_in[4];
    const float* b2  = (const float*)d_in[5];
    const float* W3  = (const float*)d_in[6];
    const float* b3  = (const float*)d_in[7];
    float*       out = (float*)d_out;

    const int N = in_sizes[0] / DIN;
    const int E = in_sizes[1] / 2;
    const int* srcp = ei;
    const int* dstp = ei + E;

    const int mtiles = (N + 127) / 128;
    const int nb = (N + SCAN_B - 1) / SCAN_B;

    static cudaStream_t s2 = nullptr;
    static cudaEvent_t evF = nullptr, evCSR = nullptr;
    if (!s2) {
        cudaStreamCreateWithFlags(&s2, cudaStreamNonBlocking);
        cudaEventCreateWithFlags(&evF, cudaEventDisableTiming);
        cudaEventCreateWithFlags(&evCSR, cudaEventDisableTiming);
    }

    // Fork: weight pre-round + CSR build on side stream (hidden under G1)
    cudaEventRecord(evF, 0);
    cudaStreamWaitEvent(s2, evF, 0);
    k_round_w<<<(DH * DH + 255) / 256, 256, 0, s2>>>(W2, 0, DH * DH);
    k_round_w<<<(DH * DOUT + 255) / 256, 256, 0, s2>>>(W3, 1, DH * DOUT);
    k_zero_cnt<<<(N + 255) / 256, 256, 0, s2>>>(N);
    k_count<<<(E + 255) / 256, 256, 0, s2>>>(dstp, E, N);
    k_scan1<<<nb, SCAN_B, 0, s2>>>(N);
    k_scan2<<<1, 128, 0, s2>>>(nb);
    k_scan3<<<(N + 255) / 256, 256, 0, s2>>>(N);
    k_fill<<<(E + 255) / 256, 256, 0, s2>>>(srcp, dstp, E, N);
    cudaEventRecord(evCSR, s2);

    // Main: G1: x -> A (rounds x and W1 at load)
    k_gemm_mma<128, 1><<<dim3(DH / 128, mtiles), 256>>>(x, 0, W1, 0, N, DH, 0);
    cudaStreamWaitEvent(0, evCSR, 0);

    // g1: A -> B (rounded)
    k_gather<DH, 2, 1><<<(N + 7) / 8, 256>>>(nullptr, 0, b1, 1, 0, N);

    // G2: B -> A (no cvt: inputs pre-rounded; W from g_W2r via wSel=1)
    k_gemm_mma<128, 0><<<dim3(DH / 128, mtiles), 256>>>(nullptr, 1, nullptr, 1, N, DH, 0);

    // g2: A -> B (rounded)
    k_gather<DH, 2, 1><<<(N + 7) / 8, 256>>>(nullptr, 0, b2, 1, 0, N);

    // G3: B -> A (no cvt; W from g_W3r via wSel=2)
    k_gemm_mma<64, 0><<<dim3(DOUT / 64, mtiles), 256>>>(nullptr, 1, nullptr, 2, N, DOUT, 0);

    // g3: A -> out (full fp32)
    k_gather<DOUT, 1, 0><<<(N + 15) / 16, 256>>>((float4*)out, 1, b3, 0, 0, N);
}

// round 17
// speedup vs baseline: 1.2895x; 1.1054x over previous
#include <cuda_runtime.h>
#include <cuda_fp16.h>
#include <cstdint>

// Problem constants (fixed by the dataset)
#define MAXN   50048
#define MAXE   800000
#define DIN    256
#define DH     256
#define DOUT   64
#define SCAN_B 1024

// Scratch (static device globals — no allocation allowed).
__device__ __half g_bufA[MAXN * DH];    // GEMM out (fp16)
__device__ __half g_bufB[MAXN * DH];    // gather out (fp16)
__device__ float  g_W2r[DH * DH];       // pre-rounded (tf32) W2
__device__ float  g_W3r[DH * DOUT];     // pre-rounded (tf32) W3
__device__ float  g_dis[MAXN];          // deg^{-1/2}
__device__ int    g_cnt[MAXN];          // degree count, then fill cursor
__device__ int    g_rowp[MAXN + 1];     // CSR row pointer
__device__ int    g_blk[128];           // block sums for scan
__device__ int    g_csrc[MAXE];         // CSR src indices

__device__ __forceinline__ float tf32_rna(float x) {
    uint32_t r;
    asm("cvt.rna.tf32.f32 %0, %1;" : "=r"(r) : "f"(x));
    return __uint_as_float(r);
}

#define MMA_TF32(D, Ar, Br) \
    asm volatile("mma.sync.aligned.m16n8k8.row.col.f32.tf32.tf32.f32 " \
        "{%0,%1,%2,%3}, {%4,%5,%6,%7}, {%8,%9}, {%0,%1,%2,%3};" \
        : "+f"((D)[0]), "+f"((D)[1]), "+f"((D)[2]), "+f"((D)[3]) \
        : "r"((Ar)[0]), "r"((Ar)[1]), "r"((Ar)[2]), "r"((Ar)[3]), \
          "r"((Br)[0]), "r"((Br)[1]))

// ===========================================================================
// Weight pre-rounding (side stream, hidden under GEMM-1)
// ===========================================================================
__global__ void k_round_w(const float* __restrict__ src, int which, int n) {
    float* dst = (which == 0) ? (float*)g_W2r : (float*)g_W3r;
    int i = blockIdx.x * blockDim.x + threadIdx.x;
    if (i < n) dst[i] = tf32_rna(src[i]);
}

// ===========================================================================
// CSR build + normalization (side stream, overlapped with GEMM-1)
// ===========================================================================
__global__ void k_zero_cnt(int n) {
    int i = blockIdx.x * blockDim.x + threadIdx.x;
    if (i < n) g_cnt[i] = 0;
}

__global__ void k_count(const int* __restrict__ dst, int E, int n) {
    int e = blockIdx.x * blockDim.x + threadIdx.x;
    if (e < E) {
        unsigned d = (unsigned)dst[e];
        if (d < (unsigned)n) atomicAdd(&g_cnt[d], 1);
    }
}

__global__ void k_scan1(int n) {
    __shared__ int sh[SCAN_B];
    int i = blockIdx.x * SCAN_B + threadIdx.x;
    int v = (i < n) ? g_cnt[i] : 0;
    if (i < n) g_dis[i] = rsqrtf((float)(v + 1));
    sh[threadIdx.x] = v;
    __syncthreads();
    #pragma unroll
    for (int off = 1; off < SCAN_B; off <<= 1) {
        int t = (threadIdx.x >= off) ? sh[threadIdx.x - off] : 0;
        __syncthreads();
        sh[threadIdx.x] += t;
        __syncthreads();
    }
    if (i < n) g_rowp[i + 1] = sh[threadIdx.x];
    if (threadIdx.x == SCAN_B - 1) g_blk[blockIdx.x] = sh[SCAN_B - 1];
}

__global__ void k_scan2(int nb) {
    __shared__ int sh[128];
    int v = (threadIdx.x < nb) ? g_blk[threadIdx.x] : 0;
    sh[threadIdx.x] = v;
    __syncthreads();
    #pragma unroll
    for (int off = 1; off < 128; off <<= 1) {
        int t = (threadIdx.x >= off) ? sh[threadIdx.x - off] : 0;
        __syncthreads();
        sh[threadIdx.x] += t;
        __syncthreads();
    }
    if (threadIdx.x < nb)
        g_blk[threadIdx.x] = (threadIdx.x > 0) ? sh[threadIdx.x - 1] : 0;
}

__global__ void k_scan3(int n) {
    int i = blockIdx.x * blockDim.x + threadIdx.x;
    if (i < n) {
        g_rowp[i + 1] += g_blk[i / SCAN_B];
        g_cnt[i] = 0;
    }
    if (i == 0) g_rowp[0] = 0;
}

__global__ void k_fill(const int* __restrict__ src, const int* __restrict__ dst,
                       int E, int n) {
    int e = blockIdx.x * blockDim.x + threadIdx.x;
    if (e >= E) return;
    unsigned s = (unsigned)src[e];
    unsigned d = (unsigned)dst[e];
    if (s >= (unsigned)n || d >= (unsigned)n) return;
    int pos = g_rowp[d] + atomicAdd(&g_cnt[d], 1);
    if (pos < MAXE) g_csrc[pos] = (int)s;
}

// ===========================================================================
// tf32 mma.sync GEMM: g_bufA(fp16) = A[M,256] @ W[256,Nc]
// AHALF: 0 = A is external fp32 (x, tf32-round per ROUNDB applies to A too),
//        1 = A is g_bufB fp16 (exactly tf32-representable, no rounding).
// ROUNDB: 1 = tf32-round W at SMEM store (raw W1); 0 = W pre-rounded.
// wSel: 0 = external W arg, 1 = g_W2r, 2 = g_W3r (resolved in device code).
// ===========================================================================
template <int BN_, int AHALF, int ROUNDB>
__global__ __launch_bounds__(256) void k_gemm_mma(
    const float* __restrict__ A_ext,
    const float* __restrict__ W_ext, int wSel, int M, int Nc)
{
    const float* __restrict__ W =
        (wSel == 0) ? W_ext : ((wSel == 1) ? (const float*)g_W2r
                                           : (const float*)g_W3r);
    __half* __restrict__ C = (__half*)g_bufA;

    constexpr int WARPS_M = (BN_ == 128) ? 2 : 4;
    constexpr int MT = 8 / WARPS_M;
    constexpr int NT = 4;
    constexpr int F4R = BN_ / 4;
    constexpr int B_IT = BN_ / 32;

    __shared__ float As[128][40];
    __shared__ float Bs[32][BN_ + 8];

    const int tid = threadIdx.x;
    const int lane = tid & 31;
    const int wid = tid >> 5;
    const int wm = wid % WARPS_M;
    const int wn = wid / WARPS_M;
    const int gid = lane >> 2;
    const int tig = lane & 3;
    const int rowBase = blockIdx.y * 128;
    const int colBase = blockIdx.x * BN_;

    // fp32-A loader coords (4 iters x float4)
    const int la_row = tid >> 3;
    const int la_c4  = tid & 7;
    // fp16-A loader coords (2 iters x uint4 = 8 halves)
    const int lh_row = tid >> 2;           // 0..63, +64 per iter
    const int lh_c8  = tid & 3;
    // B loader
    const int lb_k   = tid / F4R;
    const int lb_c4  = tid % F4R;
    constexpr int LB_STEP = 256 / F4R;

    float acc[MT][NT][4];
    #pragma unroll
    for (int mt = 0; mt < MT; mt++)
        #pragma unroll
        for (int nt = 0; nt < NT; nt++)
            #pragma unroll
            for (int j = 0; j < 4; j++) acc[mt][nt][j] = 0.0f;

    float4 pa[4];
    uint4  ph[2];
    float4 pb[B_IT];

    if (AHALF) {
        const uint4* A16 = (const uint4*)g_bufB;   // row stride 32 uint4
        #pragma unroll
        for (int i = 0; i < 2; i++) {
            int grow = rowBase + lh_row + i * 64;
            ph[i] = (grow < M) ? A16[grow * 32 + lh_c8]
                               : make_uint4(0u, 0u, 0u, 0u);
        }
    } else {
        #pragma unroll
        for (int i = 0; i < 4; i++) {
            int grow = rowBase + la_row + i * 32;
            pa[i] = (grow < M)
                ? ((const float4*)A_ext)[(long long)grow * 64 + la_c4]
                : make_float4(0.f, 0.f, 0.f, 0.f);
        }
    }
    #pragma unroll
    for (int i = 0; i < B_IT; i++) {
        int k = lb_k + i * LB_STEP;
        pb[i] = *(const float4*)(W + (long long)k * Nc + colBase + lb_c4 * 4);
    }

    #pragma unroll 1
    for (int kb = 0; kb < 8; kb++) {
        if (AHALF) {
            #pragma unroll
            for (int i = 0; i < 2; i++) {
                const __half2* hp = reinterpret_cast<const __half2*>(&ph[i]);
                float* dst = &As[lh_row + i * 64][lh_c8 * 8];
                #pragma unroll
                for (int j = 0; j < 4; j++) {
                    float2 f = __half22float2(hp[j]);
                    dst[2 * j] = f.x; dst[2 * j + 1] = f.y;
                }
            }
        } else {
            #pragma unroll
            for (int i = 0; i < 4; i++) {
                float4 v = pa[i];
                v.x = tf32_rna(v.x); v.y = tf32_rna(v.y);
                v.z = tf32_rna(v.z); v.w = tf32_rna(v.w);
                *(float4*)&As[la_row + i * 32][la_c4 * 4] = v;
            }
        }
        #pragma unroll
        for (int i = 0; i < B_IT; i++) {
            float4 v = pb[i];
            if (ROUNDB) {
                v.x = tf32_rna(v.x); v.y = tf32_rna(v.y);
                v.z = tf32_rna(v.z); v.w = tf32_rna(v.w);
            }
            *(float4*)&Bs[lb_k + i * LB_STEP][lb_c4 * 4] = v;
        }
        __syncthreads();

        if (kb < 7) {
            if (AHALF) {
                const uint4* A16 = (const uint4*)g_bufB;
                #pragma unroll
                for (int i = 0; i < 2; i++) {
                    int grow = rowBase + lh_row + i * 64;
                    ph[i] = (grow < M)
                        ? A16[grow * 32 + (kb + 1) * 4 + lh_c8]
                        : make_uint4(0u, 0u, 0u, 0u);
                }
            } else {
                #pragma unroll
                for (int i = 0; i < 4; i++) {
                    int grow = rowBase + la_row + i * 32;
                    pa[i] = (grow < M)
                        ? ((const float4*)A_ext)[(long long)grow * 64 + (kb + 1) * 8 + la_c4]
                        : make_float4(0.f, 0.f, 0.f, 0.f);
                }
            }
            #pragma unroll
            for (int i = 0; i < B_IT; i++) {
                int k = (kb + 1) * 32 + lb_k + i * LB_STEP;
                pb[i] = *(const float4*)(W + (long long)k * Nc + colBase + lb_c4 * 4);
            }
        }

        #pragma unroll
        for (int ks = 0; ks < 4; ks++) {
            int k0 = ks * 8;
            uint32_t af[MT][4], bf[NT][2];
            #pragma unroll
            for (int mt = 0; mt < MT; mt++) {
                int m0 = wm * (MT * 16) + mt * 16 + gid;
                af[mt][0] = __float_as_uint(As[m0][k0 + tig]);
                af[mt][1] = __float_as_uint(As[m0 + 8][k0 + tig]);
                af[mt][2] = __float_as_uint(As[m0][k0 + tig + 4]);
                af[mt][3] = __float_as_uint(As[m0 + 8][k0 + tig + 4]);
            }
            #pragma unroll
            for (int nt = 0; nt < NT; nt++) {
                int n0 = wn * 32 + nt * 8 + gid;
                bf[nt][0] = __float_as_uint(Bs[k0 + tig][n0]);
                bf[nt][1] = __float_as_uint(Bs[k0 + tig + 4][n0]);
            }
            #pragma unroll
            for (int mt = 0; mt < MT; mt++)
                #pragma unroll
                for (int nt = 0; nt < NT; nt++)
                    MMA_TF32(acc[mt][nt], af[mt], bf[nt]);
        }
        __syncthreads();
    }

    // Epilogue: fp16 store (half2 per fragment pair)
    #pragma unroll
    for (int mt = 0; mt < MT; mt++) {
        int r0 = rowBase + wm * (MT * 16) + mt * 16 + gid;
        int r1 = r0 + 8;
        #pragma unroll
        for (int nt = 0; nt < NT; nt++) {
            int c = colBase + wn * 32 + nt * 8 + tig * 2;
            if (r0 < M)
                *(__half2*)(C + (long long)r0 * Nc + c)
                    = __floats2half2_rn(acc[mt][nt][0], acc[mt][nt][1]);
            if (r1 < M)
                *(__half2*)(C + (long long)r1 * Nc + c)
                    = __floats2half2_rn(acc[mt][nt][2], acc[mt][nt][3]);
        }
    }
}

// ===========================================================================
// CSR gather (fp16 rows): src = g_bufA (fp16). Each thread: 8 halves (uint4).
// OUTF32: 1 -> write fp32 to dst_ext (final layer); 0 -> fp16 to g_bufB.
//   out[i] = dis[i]*( dis[i]*h[i] + sum_s dis[s]*h[s] ) + b  (fp32 accum)
// ===========================================================================
template <int F, int OUTF32>
__global__ __launch_bounds__(256) void k_gather(
    float* __restrict__ dst_ext, const float* __restrict__ bias,
    int do_relu, int n)
{
    const int L = F / 8;                       // lanes per node (uint4 each)
    const uint4* __restrict__ hs = (const uint4*)g_bufA;

    int node = blockIdx.x * (256 / L) + threadIdx.x / L;
    if (node >= n) return;
    int lane = threadIdx.x % L;

    float dd = g_dis[node];
    float acc[8];
    {
        uint4 q = hs[node * L + lane];
        const __half2* hp = reinterpret_cast<const __half2*>(&q);
        #pragma unroll
        for (int j = 0; j < 4; j++) {
            float2 f = __half22float2(hp[j]);
            acc[2 * j] = f.x * dd; acc[2 * j + 1] = f.y * dd;
        }
    }

    int p0 = g_rowp[node], p1 = g_rowp[node + 1];
    int p = p0;
    for (; p + 3 < p1; p += 4) {
        int s0 = g_csrc[p + 0];
        int s1 = g_csrc[p + 1];
        int s2 = g_csrc[p + 2];
        int s3 = g_csrc[p + 3];
        float w0 = g_dis[s0], w1 = g_dis[s1], w2 = g_dis[s2], w3 = g_dis[s3];
        uint4 q0 = hs[s0 * L + lane];
        uint4 q1 = hs[s1 * L + lane];
        uint4 q2 = hs[s2 * L + lane];
        uint4 q3 = hs[s3 * L + lane];
        const __half2* h0 = reinterpret_cast<const __half2*>(&q0);
        const __half2* h1 = reinterpret_cast<const __half2*>(&q1);
        const __half2* h2 = reinterpret_cast<const __half2*>(&q2);
        const __half2* h3 = reinterpret_cast<const __half2*>(&q3);
        #pragma unroll
        for (int j = 0; j < 4; j++) {
            float2 f0 = __half22float2(h0[j]);
            float2 f1 = __half22float2(h1[j]);
            float2 f2 = __half22float2(h2[j]);
            float2 f3 = __half22float2(h3[j]);
            acc[2 * j]     += (f0.x * w0 + f1.x * w1) + (f2.x * w2 + f3.x * w3);
            acc[2 * j + 1] += (f0.y * w0 + f1.y * w1) + (f2.y * w2 + f3.y * w3);
        }
    }
    for (; p < p1; p++) {
        int s = g_csrc[p];
        float w = g_dis[s];
        uint4 q = hs[s * L + lane];
        const __half2* hp = reinterpret_cast<const __half2*>(&q);
        #pragma unroll
        for (int j = 0; j < 4; j++) {
            float2 f = __half22float2(hp[j]);
            acc[2 * j] += f.x * w; acc[2 * j + 1] += f.y * w;
        }
    }

    float o[8];
    {
        float4 b0 = ((const float4*)bias)[lane * 2];
        float4 b1 = ((const float4*)bias)[lane * 2 + 1];
        o[0] = acc[0] * dd + b0.x; o[1] = acc[1] * dd + b0.y;
        o[2] = acc[2] * dd + b0.z; o[3] = acc[3] * dd + b0.w;
        o[4] = acc[4] * dd + b1.x; o[5] = acc[5] * dd + b1.y;
        o[6] = acc[6] * dd + b1.z; o[7] = acc[7] * dd + b1.w;
    }
    if (do_relu) {
        #pragma unroll
        for (int j = 0; j < 8; j++) o[j] = fmaxf(o[j], 0.0f);
    }

    if (OUTF32) {
        float* dst = dst_ext + (long long)node * F + lane * 8;
        *(float4*)(dst)     = make_float4(o[0], o[1], o[2], o[3]);
        *(float4*)(dst + 4) = make_float4(o[4], o[5], o[6], o[7]);
    } else {
        uint4 q;
        __half2 t;
        t = __floats2half2_rn(o[0], o[1]); q.x = *reinterpret_cast<uint32_t*>(&t);
        t = __floats2half2_rn(o[2], o[3]); q.y = *reinterpret_cast<uint32_t*>(&t);
        t = __floats2half2_rn(o[4], o[5]); q.z = *reinterpret_cast<uint32_t*>(&t);
        t = __floats2half2_rn(o[6], o[7]); q.w = *reinterpret_cast<uint32_t*>(&t);
        ((uint4*)g_bufB)[node * L + lane] = q;
    }
}

// ===========================================================================
// Launch: R8 linear schedule.  x -G1-> A -g1-> B -G2-> A -g2-> B -G3-> A
// -g3-> out.  CSR build + weight pre-round ∥ G1 on side stream.
// All intermediates fp16 (exactly tf32-representable -> only one extra
// rounding per layer vs pure-fp32 pipeline).
// ===========================================================================
extern "C" void kernel_launch(void* const* d_in, const int* in_sizes, int n_in,
                              void* d_out, int out_size)
{
    const float* x   = (const float*)d_in[0];
    const int*   ei  = (const int*)d_in[1];
    const float* W1  = (const float*)d_in[2];
    const float* b1  = (const float*)d_in[3];
    const float* W2  = (const float*)d_in[4];
    const float* b2  = (const float*)d_in[5];
    const float* W3  = (const float*)d_in[6];
    const float* b3  = (const float*)d_in[7];
    float*       out = (float*)d_out;

    const int N = in_sizes[0] / DIN;
    const int E = in_sizes[1] / 2;
    const int* srcp = ei;
    const int* dstp = ei + E;

    const int mtiles = (N + 127) / 128;
    const int nb = (N + SCAN_B - 1) / SCAN_B;

    static cudaStream_t s2 = nullptr;
    static cudaEvent_t evF = nullptr, evCSR = nullptr;
    if (!s2) {
        cudaStreamCreateWithFlags(&s2, cudaStreamNonBlocking);
        cudaEventCreateWithFlags(&evF, cudaEventDisableTiming);
        cudaEventCreateWithFlags(&evCSR, cudaEventDisableTiming);
    }

    // Fork: weight pre-round + CSR build on side stream (hidden under G1)
    cudaEventRecord(evF, 0);
    cudaStreamWaitEvent(s2, evF, 0);
    k_round_w<<<(DH * DH + 255) / 256, 256, 0, s2>>>(W2, 0, DH * DH);
    k_round_w<<<(DH * DOUT + 255) / 256, 256, 0, s2>>>(W3, 1, DH * DOUT);
    k_zero_cnt<<<(N + 255) / 256, 256, 0, s2>>>(N);
    k_count<<<(E + 255) / 256, 256, 0, s2>>>(dstp, E, N);
    k_scan1<<<nb, SCAN_B, 0, s2>>>(N);
    k_scan2<<<1, 128, 0, s2>>>(nb);
    k_scan3<<<(N + 255) / 256, 256, 0, s2>>>(N);
    k_fill<<<(E + 255) / 256, 256, 0, s2>>>(srcp, dstp, E, N);
    cudaEventRecord(evCSR, s2);

    // G1: x (fp32, tf32-rounded) @ W1 -> bufA (fp16)
    k_gemm_mma<128, 0, 1><<<dim3(DH / 128, mtiles), 256>>>(x, W1, 0, N, DH);
    cudaStreamWaitEvent(0, evCSR, 0);

    // g1: bufA -> bufB (fp16)
    k_gather<DH, 0><<<(N + 7) / 8, 256>>>(nullptr, b1, 1, N);

    // G2: bufB (fp16) @ W2r -> bufA (fp16)
    k_gemm_mma<128, 1, 0><<<dim3(DH / 128, mtiles), 256>>>(nullptr, nullptr, 1, N, DH);

    // g2: bufA -> bufB (fp16)
    k_gather<DH, 0><<<(N + 7) / 8, 256>>>(nullptr, b2, 1, N);

    // G3: bufB (fp16) @ W3r -> bufA (fp16, 64-wide)
    k_gemm_mma<64, 1, 0><<<dim3(DOUT / 64, mtiles), 256>>>(nullptr, nullptr, 2, N, DOUT);

    // g3: bufA -> out (fp32)
    k_gather<DOUT, 1><<<(N + 31) / 32, 256>>>(out, b3, 0, N);
}